// round 1
// baseline (speedup 1.0000x reference)
#include <cuda_runtime.h>
#include <math.h>

// Problem constants (fixed-shape problem; runtime values checked against these caps)
#define NQ_C 2048
#define NT_C 131072
#define D_C 64
#define E_C 2000000
#define M_C 1024
#define NBLK_SCAN 128   // NT_C / 1024

// ---------------- scratch (static device globals; no allocation) ----------------
__device__ float g_yqab[NQ_C * 128];   // per-u row: pairs (ya[2p], yb[2p], ya[2p+1], yb[2p+1])
__device__ int   g_deg[NT_C];
__device__ int   g_off[NT_C + 1];
__device__ int   g_cursor[NT_C];
__device__ int   g_usort[E_C];
__device__ int   g_bsum[NBLK_SCAN];

#define FULLM 0xffffffffu

// ---------------- setup kernels ----------------
__global__ void zero_deg_kernel(int NT) {
    int i = blockIdx.x * blockDim.x + threadIdx.x;
    if (i < NT) g_deg[i] = 0;
}

__global__ void count_kernel(const int* __restrict__ v_idx, int E) {
    int stride = gridDim.x * blockDim.x;
    for (int i = blockIdx.x * blockDim.x + threadIdx.x; i < E; i += stride)
        atomicAdd(&g_deg[v_idx[i]], 1);
}

// block-local exclusive scan over 1024 elements; block totals to g_bsum
__global__ void scan1_kernel(int NT) {
    __shared__ int wsum[32];
    int tid = threadIdx.x;
    int lane = tid & 31, wid = tid >> 5;
    int i = blockIdx.x * 1024 + tid;
    int v = (i < NT) ? g_deg[i] : 0;
    int x = v;
#pragma unroll
    for (int d = 1; d < 32; d <<= 1) {
        int y = __shfl_up_sync(FULLM, x, d);
        if (lane >= d) x += y;
    }
    if (lane == 31) wsum[wid] = x;
    __syncthreads();
    if (wid == 0) {
        int w = wsum[lane];
#pragma unroll
        for (int d = 1; d < 32; d <<= 1) {
            int y = __shfl_up_sync(FULLM, w, d);
            if (lane >= d) w += y;
        }
        wsum[lane] = w;
    }
    __syncthreads();
    int excl = x - v + (wid ? wsum[wid - 1] : 0);
    if (i < NT) g_off[i] = excl;
    if (tid == 0) g_bsum[blockIdx.x] = wsum[31];
}

// exclusive scan of the (<=128) block sums; single block of 128 threads
__global__ void scan2_kernel(int nb) {
    __shared__ int wsum[4];
    int tid = threadIdx.x;
    int lane = tid & 31, wid = tid >> 5;
    int v = (tid < nb) ? g_bsum[tid] : 0;
    int x = v;
#pragma unroll
    for (int d = 1; d < 32; d <<= 1) {
        int y = __shfl_up_sync(FULLM, x, d);
        if (lane >= d) x += y;
    }
    if (lane == 31) wsum[wid] = x;
    __syncthreads();
    int add = 0;
    for (int k = 0; k < wid; ++k) add += wsum[k];
    g_bsum[tid] = x - v + add;   // exclusive
}

__global__ void scan3_kernel(int NT, int E) {
    int i = blockIdx.x * blockDim.x + threadIdx.x;
    if (i < NT) {
        int o = g_off[i] + g_bsum[i >> 10];
        g_off[i] = o;
        g_cursor[i] = o;
    }
    if (i == 0) g_off[NT] = E;
}

__global__ void scatter_kernel(const int* __restrict__ u_idx,
                               const int* __restrict__ v_idx, int E) {
    int stride = gridDim.x * blockDim.x;
    for (int i = blockIdx.x * blockDim.x + threadIdx.x; i < E; i += stride) {
        int v = v_idx[i];
        int slot = atomicAdd(&g_cursor[v], 1);
        g_usort[slot] = u_idx[i];
    }
}

// Yqa = Xq @ W_alpha, Yqb = Xq @ W_beta, stored interleaved per row:
// g_yqab[u*128 + 4p + {0,1,2,3}] = (ya[2p], yb[2p], ya[2p+1], yb[2p+1])
__global__ void yq_kernel(const float* __restrict__ Xq,
                          const float* __restrict__ Wa,
                          const float* __restrict__ Wb) {
    __shared__ float sx[64];
    int r = blockIdx.x;
    int j = threadIdx.x;   // 64 threads
    sx[j] = Xq[(size_t)r * 64 + j];
    __syncthreads();
    float a = 0.f, b = 0.f;
#pragma unroll
    for (int d = 0; d < 64; ++d) {
        float x = sx[d];
        a = fmaf(x, Wa[d * 64 + j], a);
        b = fmaf(x, Wb[d * 64 + j], b);
    }
    int p = j >> 1, hi = j & 1;
    g_yqab[(size_t)r * 128 + 4 * p + 2 * hi + 0] = a;
    g_yqab[(size_t)r * 128 + 4 * p + 2 * hi + 1] = b;
}

// ---------------- main per-target kernel ----------------
// Computes alpha/beta for one 32-edge chunk of target v.
// Lane l owns edge (start+l) for l<cnt. All 32 lanes cooperate per edge dot.
__device__ __forceinline__ void compute_chunk(
    int start, int cnt, float2 xv, float bav, float bbv, int lane,
    float& a_l, float& b_l, int& u_l)
{
    u_l = (lane < cnt) ? g_usort[start + lane] : 0;
    a_l = 0.f; b_l = 0.f;
    for (int j = 0; j < cnt; ++j) {
        int uj = __shfl_sync(FULLM, u_l, j);
        const float4 y = *(reinterpret_cast<const float4*>(g_yqab + (size_t)uj * 128) + lane);
        float pa = fmaf(y.x, xv.x, y.z * xv.y);
        float pb = fmaf(y.y, xv.x, y.w * xv.y);
#pragma unroll
        for (int s = 16; s > 0; s >>= 1) {
            pa += __shfl_xor_sync(FULLM, pa, s);
            pb += __shfl_xor_sync(FULLM, pb, s);
        }
        float da = pa + bav;
        float db = pb + bbv;
        float alpha = (da > 0.f) ? da : expm1f(da);
        float beta  = 1.0f / (1.0f + expf(-db));
        if (j == lane) { a_l = alpha; b_l = beta; }
    }
}

__global__ __launch_bounds__(256) void main_kernel(
    const float* __restrict__ Xq, const float* __restrict__ Xt,
    const float* __restrict__ ba, const float* __restrict__ bb,
    float* __restrict__ outXt, int NT)
{
    int warpId = threadIdx.x >> 5;
    int lane   = threadIdx.x & 31;
    int v = blockIdx.x * 8 + warpId;
    if (v >= NT) return;

    int o   = g_off[v];
    int deg = g_off[v + 1] - o;
    const float* xrow = Xt + (size_t)v * 64;
    float xt0 = xrow[lane];
    float xt1 = xrow[32 + lane];
    float* orow = outXt + (size_t)v * 64;

    if (deg == 0) {
        orow[lane] = xt0;
        orow[32 + lane] = xt1;
        return;
    }

    float2 xv = reinterpret_cast<const float2*>(xrow)[lane];
    float bav = __ldg(ba);
    float bbv = __ldg(bb);

    int nch = (deg + 31) >> 5;

    // ---- pass 1: compute alpha/beta per edge (chunk0 kept in regs), segment max ----
    float a0 = 0.f, b0 = 0.f; int u0 = 0;
    float m = __int_as_float(0xff800000);  // -inf
    for (int c = 0; c < nch; ++c) {
        int start = o + c * 32;
        int cnt = deg - c * 32; if (cnt > 32) cnt = 32;
        float a_l, b_l; int u_l;
        compute_chunk(start, cnt, xv, bav, bbv, lane, a_l, b_l, u_l);
        if (c == 0) { a0 = a_l; b0 = b_l; u0 = u_l; }
        float t = (lane < cnt) ? a_l : __int_as_float(0xff800000);
#pragma unroll
        for (int s = 16; s > 0; s >>= 1) t = fmaxf(t, __shfl_xor_sync(FULLM, t, s));
        m = fmaxf(m, t);
    }

    // ---- pass 2: segment sum of exp(alpha - m) ----
    float ssum = 0.f;
    for (int c = 0; c < nch; ++c) {
        int start = o + c * 32;
        int cnt = deg - c * 32; if (cnt > 32) cnt = 32;
        float a_l, b_l; int u_l;
        if (c == 0) { a_l = a0; b_l = b0; u_l = u0; }
        else compute_chunk(start, cnt, xv, bav, bbv, lane, a_l, b_l, u_l);
        float t = (lane < cnt) ? expf(a_l - m) : 0.f;
#pragma unroll
        for (int s = 16; s > 0; s >>= 1) t += __shfl_xor_sync(FULLM, t, s);
        ssum += t;
    }

    // ---- pass 3: weighted aggregation ----
    // agg = sum_j w_j*(1-beta_j)*Xq[u_j]  +  (sum_j w_j*beta_j) * xt_v
    float acc0 = 0.f, acc1 = 0.f, swb = 0.f;
    for (int c = 0; c < nch; ++c) {
        int start = o + c * 32;
        int cnt = deg - c * 32; if (cnt > 32) cnt = 32;
        float a_l, b_l; int u_l;
        if (c == 0) { a_l = a0; b_l = b0; u_l = u0; }
        else compute_chunk(start, cnt, xv, bav, bbv, lane, a_l, b_l, u_l);
        float w  = (lane < cnt) ? (expf(a_l - m) / ssum + 1e-10f) : 0.f;
        float wb = w * b_l;
        float cb = w - wb;     // w * (1 - beta)
        swb += wb;

        int j = 0;
        for (; j + 4 <= cnt; j += 4) {
            int uu0 = __shfl_sync(FULLM, u_l, j + 0);
            int uu1 = __shfl_sync(FULLM, u_l, j + 1);
            int uu2 = __shfl_sync(FULLM, u_l, j + 2);
            int uu3 = __shfl_sync(FULLM, u_l, j + 3);
            float c0 = __shfl_sync(FULLM, cb, j + 0);
            float c1 = __shfl_sync(FULLM, cb, j + 1);
            float c2 = __shfl_sync(FULLM, cb, j + 2);
            float c3 = __shfl_sync(FULLM, cb, j + 3);
            const float* r0 = Xq + (size_t)uu0 * 64;
            const float* r1 = Xq + (size_t)uu1 * 64;
            const float* r2 = Xq + (size_t)uu2 * 64;
            const float* r3 = Xq + (size_t)uu3 * 64;
            float x00 = r0[lane], x01 = r0[32 + lane];
            float x10 = r1[lane], x11 = r1[32 + lane];
            float x20 = r2[lane], x21 = r2[32 + lane];
            float x30 = r3[lane], x31 = r3[32 + lane];
            acc0 = fmaf(c0, x00, acc0); acc1 = fmaf(c0, x01, acc1);
            acc0 = fmaf(c1, x10, acc0); acc1 = fmaf(c1, x11, acc1);
            acc0 = fmaf(c2, x20, acc0); acc1 = fmaf(c2, x21, acc1);
            acc0 = fmaf(c3, x30, acc0); acc1 = fmaf(c3, x31, acc1);
        }
        for (; j < cnt; ++j) {
            int   uu = __shfl_sync(FULLM, u_l, j);
            float cc = __shfl_sync(FULLM, cb, j);
            const float* r = Xq + (size_t)uu * 64;
            acc0 = fmaf(cc, r[lane], acc0);
            acc1 = fmaf(cc, r[32 + lane], acc1);
        }
    }
#pragma unroll
    for (int s = 16; s > 0; s >>= 1) swb += __shfl_xor_sync(FULLM, swb, s);

    orow[lane]      = fmaf(swb, xt0, acc0);
    orow[32 + lane] = fmaf(swb, xt1, acc1);
}

// consensus overwrite (last): outXt[vc[m]] = Xq[uc[m]]
__global__ void consensus_kernel(const float* __restrict__ Xq,
                                 const int* __restrict__ uc,
                                 const int* __restrict__ vc,
                                 float* __restrict__ outXt, int M) {
    int i = blockIdx.x * blockDim.x + threadIdx.x;
    if (i >= M * 64) return;
    int mrow = i >> 6, d = i & 63;
    outXt[(size_t)vc[mrow] * 64 + d] = Xq[(size_t)uc[mrow] * 64 + d];
}

// ---------------- launcher ----------------
extern "C" void kernel_launch(void* const* d_in, const int* in_sizes, int n_in,
                              void* d_out, int out_size) {
    const float* Xq = (const float*)d_in[0];
    const float* Xt = (const float*)d_in[1];
    const float* Wa = (const float*)d_in[2];
    const float* ba = (const float*)d_in[3];
    const float* Wb = (const float*)d_in[4];
    const float* bb = (const float*)d_in[5];
    const int* u_idx = (const int*)d_in[6];
    const int* v_idx = (const int*)d_in[7];
    const int* uc = (const int*)d_in[8];
    const int* vc = (const int*)d_in[9];

    int NQ = in_sizes[0] / 64;
    int NT = in_sizes[1] / 64;
    int E  = in_sizes[6];
    int M  = in_sizes[8];

    float* out = (float*)d_out;
    float* outXt = out + (size_t)NQ * 64;

    // CSR build
    zero_deg_kernel<<<(NT + 255) / 256, 256>>>(NT);
    count_kernel<<<2048, 256>>>(v_idx, E);
    int nb = (NT + 1023) / 1024;
    scan1_kernel<<<nb, 1024>>>(NT);
    scan2_kernel<<<1, 128>>>(nb);
    scan3_kernel<<<(NT + 255) / 256, 256>>>(NT, E);
    scatter_kernel<<<2048, 256>>>(u_idx, v_idx, E);

    // precompute Yq projections
    yq_kernel<<<NQ, 64>>>(Xq, Wa, Wb);

    // out[0 : NQ*D] = Xq
    cudaMemcpyAsync(out, Xq, (size_t)NQ * 64 * sizeof(float),
                    cudaMemcpyDeviceToDevice, 0);

    // main pass: one warp per target
    main_kernel<<<(NT + 7) / 8, 256>>>(Xq, Xt, ba, bb, outXt, NT);

    // consensus rows last
    consensus_kernel<<<(M * 64 + 255) / 256, 256>>>(Xq, uc, vc, outXt, M);
}